// round 7
// baseline (speedup 1.0000x reference)
#include <cuda_runtime.h>
#include <math.h>

// Problem constants
#define SS        26
#define CC        80
#define CELLS     676        // 26*26
#define NB        32
#define BIMG      256
#define OBJCELLS  2028       // 3*676
#define NWORDS    (OBJCELLS/4)   // 507 float4 words
#define NCH       255        // 3*(5+80)
#define DIV       16.0f      // 416/26
#define INV_IMG   (1.0f/416.0f)
#define NTHR      256
#define NSLICE    4
#define GRID      (BIMG*NSLICE)      // 1024
#define LBL_PER_SLICE ((NB*CC)/NSLICE)  // 640
#define WPS       127                // noobj words per slice (last slice gets 126)

__constant__ float c_anchor[18] = {
    10.f,13.f, 16.f,30.f, 33.f,23.f, 30.f,61.f, 62.f,45.f,
    59.f,119.f, 116.f,90.f, 156.f,198.f, 373.f,326.f
};

__device__ float g_partial[GRID];
__device__ unsigned int g_done_count = 0;

// L2 evict_last via cache-policy register
__device__ __forceinline__ unsigned long long mk_policy() {
    unsigned long long pol;
    asm volatile("createpolicy.fractional.L2::evict_last.b64 %0, 1.0;" : "=l"(pol));
    return pol;
}
__device__ __forceinline__ float ldg_el(const float* p, unsigned long long pol) {
    float v;
    asm volatile("ld.global.nc.L2::cache_hint.f32 %0, [%1], %2;"
                 : "=f"(v) : "l"(p), "l"(pol));
    return v;
}
__device__ __forceinline__ float4 ldg_el4(const float* p, unsigned long long pol) {
    float4 v;
    asm volatile("ld.global.nc.L2::cache_hint.v4.f32 {%0,%1,%2,%3}, [%4], %5;"
                 : "=f"(v.x), "=f"(v.y), "=f"(v.z), "=f"(v.w) : "l"(p), "l"(pol));
    return v;
}

__global__ void __launch_bounds__(NTHR)
yolo_sliced_kernel(const float* __restrict__ bx,
                   const float* __restrict__ bbox,
                   const int*   __restrict__ bidx,
                   float* __restrict__ out)
{
    const int blk  = blockIdx.x;
    const int b    = blk >> 2;       // image
    const int s    = blk & 3;        // slice within image
    const int tid  = threadIdx.x;
    const int warp = tid >> 5;
    const int lane = tid & 31;
    const float* __restrict__ x = bx + (size_t)b * NCH * CELLS;
    const unsigned long long pol = mk_policy();

    __shared__ int   s_base[NB];
    __shared__ int   s_o[NB];
    __shared__ int   s_cls[NB];
    __shared__ unsigned int cleared32[NWORDS];   // byte flags packed 4/word
    __shared__ float sredA[8];
    __shared__ float sredN[8];
    __shared__ int   sredC[8];
    __shared__ int   s_last;

    unsigned char* cleared = (unsigned char*)cleared32;

    for (int j = tid; j < NWORDS; j += NTHR) cleared32[j] = 0u;
    __syncthreads();

    float acc = 0.0f;   // per-thread pre-weighted loss accumulator

    // Phase 1: geometry for all 32 boxes (cheap, coalesced bbox reads)
    if (tid < NB) {
        const int i = tid;
        const float* bp = bbox + ((size_t)b * NB + i) * 5;
        float cls = bp[0], cx = bp[1], cy = bp[2], w = bp[3], h = bp[4];
        int nidx = bidx[b * NB + i];
        int now  = nidx - 3;
        int base = now * 85;
        int ix = (int)(cx / DIV);
        int iy = (int)(cy / DIV);
        float ax = (cx - (float)ix * DIV) / DIV;
        float ay = (cy - (float)iy * DIV) / DIV;
        int o = ix * SS + iy;

        s_base[i] = base;
        s_o[i]    = o;
        s_cls[i]  = (int)cls;
        cleared[now * CELLS + o] = 1;   // racy duplicate writes of 1 -> benign

        if (s == 0) {
            // slice 0 pays for the 5 head gathers + coord/obj loss
            const float* p = x + (size_t)base * CELLS + o;
            float obj_pred = ldg_el(p + 0 * CELLS, pol);
            float rax      = ldg_el(p + 1 * CELLS, pol);
            float ray      = ldg_el(p + 2 * CELLS, pol);
            float t3       = ldg_el(p + 3 * CELLS, pol);
            float t4       = ldg_el(p + 4 * CELLS, pol);

            float sig3 = 1.0f / (1.0f + __expf(-t3));
            float sig4 = 1.0f / (1.0f + __expf(-t4));
            float rw = c_anchor[nidx * 2 + 0] * __expf(4.0f * sig3 - 2.0f);
            float rh = c_anchor[nidx * 2 + 1] * __expf(4.0f * sig4 - 2.0f);

            // IOU with the reference's +1 offsets
            float b1x0 = rax * DIV - rw * 0.5f, b1y0 = ray * DIV - rh * 0.5f;
            float b1x1 = rax * DIV + rw * 0.5f, b1y1 = ray * DIV + rh * 0.5f;
            float b2x0 = ax  * DIV - w  * 0.5f, b2y0 = ay  * DIV - h  * 0.5f;
            float b2x1 = ax  * DIV + w  * 0.5f, b2y1 = ay  * DIV + h  * 0.5f;

            float A  = (b1x1 - b1x0 + 1.0f) * (b1y1 - b1y0 + 1.0f);
            float Bt = (b2x1 - b2x0 + 1.0f) * (b2y1 - b2y0 + 1.0f);
            float CM = (fminf(b1x1, b2x1) - fmaxf(b1x0, b2x0) + 1.0f)
                     * (fminf(b1y1, b2y1) - fmaxf(b1y0, b2y0) + 1.0f);
            float iou = CM / (A + Bt - CM);
            iou = (iou < 0.0f) ? 0.0f : iou;

            float d0 = obj_pred - iou;
            float d1 = rax - ax;
            float d2 = ray - ay;
            float d3 = (rw - w) * INV_IMG;
            float d4 = (rh - h) * INV_IMG;

            acc += 5.0f * (d0*d0 + d1*d1 + d2*d2 + d3*d3 + d4*d4) * (1.0f / NB);
        }
    }
    __syncthreads();

    // Phase 2: this slice's 640 label gathers (2-3 independent loads per thread)
    {
        float lacc = 0.0f;
        #pragma unroll 3
        for (int idx = s * LBL_PER_SLICE + tid; idx < (s + 1) * LBL_PER_SLICE; idx += NTHR) {
            int i = idx / CC;
            int c = idx - i * CC;
            float val = ldg_el(x + (size_t)(s_base[i] + 5 + c) * CELLS + s_o[i], pol);
            float hot = (c == s_cls[i]) ? 1.0f : 0.0f;
            float d = val - hot;
            lacc += d * d;
        }
        acc += lacc * (1.0f / (NB * CC));
    }

    // Phase 3: noobj — contiguous, coalesced quarter of the 507 float4 words
    float no = 0.0f;
    {
        int j4 = s * WPS + tid;              // tid < WPS covers this slice's words
        if (tid < WPS && j4 < NWORDS) {
            int r    = j4 / (CELLS / 4);
            int rem4 = j4 - r * (CELLS / 4);
            const float4 v = ldg_el4(x + (size_t)(r * 85) * CELLS + rem4 * 4, pol);
            unsigned int m = cleared32[j4];
            if (!(m & 0x000000FFu)) no += v.x * v.x;
            if (!(m & 0x0000FF00u)) no += v.y * v.y;
            if (!(m & 0x00FF0000u)) no += v.z * v.z;
            if (!(m & 0xFF000000u)) no += v.w * v.w;
        }
    }

    // Dedup count (each slice computes the identical count; 2 words/thread)
    int ccount = __popc(cleared32[tid < NWORDS ? tid : 0]) * (tid < NWORDS ? 1 : 0);
    {
        int j = tid + NTHR;
        if (j < NWORDS) ccount += __popc(cleared32[j]);
    }

    // Deterministic warp-shuffle + cross-warp reduction
    #pragma unroll
    for (int off = 16; off > 0; off >>= 1) {
        acc    += __shfl_down_sync(0xFFFFFFFFu, acc,    off);
        no     += __shfl_down_sync(0xFFFFFFFFu, no,     off);
        ccount += __shfl_down_sync(0xFFFFFFFFu, ccount, off);
    }
    if (lane == 0) { sredA[warp] = acc; sredN[warp] = no; sredC[warp] = ccount; }
    __syncthreads();

    if (tid == 0) {
        float A = 0.0f, Nn = 0.0f;
        int   Cc = 0;
        #pragma unroll
        for (int w = 0; w < 8; w++) { A += sredA[w]; Nn += sredN[w]; Cc += sredC[w]; }
        float cnt = (float)(OBJCELLS - Cc);
        g_partial[blk] = A + 0.5f * Nn / cnt;
        __threadfence();
        unsigned int old = atomicAdd(&g_done_count, 1u);
        s_last = (old == GRID - 1) ? 1 : 0;
    }
    __syncthreads();

    // Last block standing: deterministic fixed-order final reduction of 1024 partials
    if (s_last) {
        float v = g_partial[tid]
                + g_partial[tid + 256]
                + g_partial[tid + 512]
                + g_partial[tid + 768];
        #pragma unroll
        for (int off = 16; off > 0; off >>= 1)
            v += __shfl_down_sync(0xFFFFFFFFu, v, off);
        if (lane == 0) sredA[warp] = v;
        __syncthreads();
        if (tid == 0) {
            float t = 0.0f;
            #pragma unroll
            for (int w = 0; w < 8; w++) t += sredA[w];
            out[0] = t;
            atomicExch(&g_done_count, 0u);   // reset for next graph replay
        }
    }
}

extern "C" void kernel_launch(void* const* d_in, const int* in_sizes, int n_in,
                              void* d_out, int out_size)
{
    const float* bx   = (const float*)d_in[0];
    const float* bbox = (const float*)d_in[1];
    const int*   bidx = (const int*)d_in[2];
    float* out = (float*)d_out;

    yolo_sliced_kernel<<<GRID, NTHR>>>(bx, bbox, bidx, out);
}

// round 9
// speedup vs baseline: 1.3528x; 1.3528x over previous
#include <cuda_runtime.h>
#include <math.h>

// Problem constants
#define SS        26
#define CC        80
#define CELLS     676        // 26*26
#define NB        32
#define BIMG      256
#define OBJCELLS  2028       // 3*676
#define NWORDS    (OBJCELLS/4)   // 507 float4 words
#define NCH       255        // 3*(5+80)
#define DIV       16.0f      // 416/26
#define INV_IMG   (1.0f/416.0f)
#define NTHR      512

__constant__ float c_anchor[18] = {
    10.f,13.f, 16.f,30.f, 33.f,23.f, 30.f,61.f, 62.f,45.f,
    59.f,119.f, 116.f,90.f, 156.f,198.f, 373.f,326.f
};

__device__ float g_img_loss[BIMG];
__device__ unsigned int g_done_count = 0;

// L2 evict_last via cache-policy register
__device__ __forceinline__ unsigned long long mk_policy() {
    unsigned long long pol;
    asm volatile("createpolicy.fractional.L2::evict_last.b64 %0, 1.0;" : "=l"(pol));
    return pol;
}
__device__ __forceinline__ float ldg_el(const float* p, unsigned long long pol) {
    float v;
    asm volatile("ld.global.nc.L2::cache_hint.f32 %0, [%1], %2;"
                 : "=f"(v) : "l"(p), "l"(pol));
    return v;
}
__device__ __forceinline__ float4 ldg_el4(const float* p, unsigned long long pol) {
    float4 v;
    asm volatile("ld.global.nc.L2::cache_hint.v4.f32 {%0,%1,%2,%3}, [%4], %5;"
                 : "=f"(v.x), "=f"(v.y), "=f"(v.z), "=f"(v.w) : "l"(p), "l"(pol));
    return v;
}

__global__ void __launch_bounds__(NTHR)
yolo_flat_kernel(const float* __restrict__ bx,
                 const float* __restrict__ bbox,
                 const int*   __restrict__ bidx,
                 float* __restrict__ out)
{
    const int b    = blockIdx.x;
    const int tid  = threadIdx.x;
    const int warp = tid >> 5;
    const int lane = tid & 31;
    const float* __restrict__ x = bx + (size_t)b * NCH * CELLS;
    const unsigned long long pol = mk_policy();

    __shared__ unsigned int cleared32[NWORDS];   // byte flags packed 4/word
    __shared__ float sredA[16];
    __shared__ float sredN[16];
    __shared__ int   sredC[16];
    __shared__ int   s_last;

    unsigned char* cleared = (unsigned char*)cleared32;

    // Zero mask: 1 word per thread (507 <= 512)
    if (tid < NWORDS) cleared32[tid] = 0u;

    // ---- Per-thread box geometry straight from global (no smem dependency) ----
    // thread t -> box i = t>>4, classes c0 = (t&15)*5 .. c0+4
    const int i  = tid >> 4;
    const int c0 = (tid & 15) * 5;
    const bool is_head = (tid & 15) == 0;

    const float* bp = bbox + ((size_t)b * NB + i) * 5;
    float cls = bp[0], cx = bp[1], cy = bp[2], w = bp[3], h = bp[4];
    int nidx = bidx[b * NB + i];
    int now  = nidx - 3;
    int base = now * 85;
    int ix = (int)(cx / DIV);
    int iy = (int)(cy / DIV);
    float ax = (cx - (float)ix * DIV) / DIV;
    float ay = (cy - (float)iy * DIV) / DIV;
    int o = ix * SS + iy;
    int cls_i = (int)cls;

    const float* p = x + (size_t)base * CELLS + o;

    // ---- Issue ALL gathers now (label + head + noobj), fully overlapped ----
    float v0 = ldg_el(p + (size_t)(5 + c0 + 0) * CELLS, pol);
    float v1 = ldg_el(p + (size_t)(5 + c0 + 1) * CELLS, pol);
    float v2 = ldg_el(p + (size_t)(5 + c0 + 2) * CELLS, pol);
    float v3 = ldg_el(p + (size_t)(5 + c0 + 3) * CELLS, pol);
    float v4 = ldg_el(p + (size_t)(5 + c0 + 4) * CELLS, pol);

    float obj_pred = 0.f, rax = 0.f, ray = 0.f, t3 = 0.f, t4 = 0.f;
    if (is_head) {
        obj_pred = ldg_el(p + 0 * CELLS, pol);
        rax      = ldg_el(p + 1 * CELLS, pol);
        ray      = ldg_el(p + 2 * CELLS, pol);
        t3       = ldg_el(p + 3 * CELLS, pol);
        t4       = ldg_el(p + 4 * CELLS, pol);
    }

    float4 nv = make_float4(0.f, 0.f, 0.f, 0.f);
    if (tid < NWORDS) {
        int r    = tid / (CELLS / 4);
        int rem4 = tid - r * (CELLS / 4);
        nv = ldg_el4(x + (size_t)(r * 85) * CELLS + rem4 * 4, pol);
    }

    // Mask-zero fence (loads above remain in flight across the barrier)
    __syncthreads();

    // Scatter the cleared flags (32 head threads; duplicate writes of 1 benign)
    if (is_head) cleared[now * CELLS + o] = 1;

    // ---- Label MSE while mask scatter settles ----
    float acc;
    {
        float hot0 = (c0 + 0 == cls_i) ? 1.0f : 0.0f;
        float hot1 = (c0 + 1 == cls_i) ? 1.0f : 0.0f;
        float hot2 = (c0 + 2 == cls_i) ? 1.0f : 0.0f;
        float hot3 = (c0 + 3 == cls_i) ? 1.0f : 0.0f;
        float hot4 = (c0 + 4 == cls_i) ? 1.0f : 0.0f;
        float d0 = v0 - hot0, d1 = v1 - hot1, d2 = v2 - hot2,
              d3 = v3 - hot3, d4 = v4 - hot4;
        acc = (d0*d0 + d1*d1 + d2*d2 + d3*d3 + d4*d4) * (1.0f / (NB * CC));
    }

    // ---- Coord/obj loss on head threads ----
    if (is_head) {
        float sig3 = 1.0f / (1.0f + __expf(-t3));
        float sig4 = 1.0f / (1.0f + __expf(-t4));
        float rw = c_anchor[nidx * 2 + 0] * __expf(4.0f * sig3 - 2.0f);
        float rh = c_anchor[nidx * 2 + 1] * __expf(4.0f * sig4 - 2.0f);

        float b1x0 = rax * DIV - rw * 0.5f, b1y0 = ray * DIV - rh * 0.5f;
        float b1x1 = rax * DIV + rw * 0.5f, b1y1 = ray * DIV + rh * 0.5f;
        float b2x0 = ax  * DIV - w  * 0.5f, b2y0 = ay  * DIV - h  * 0.5f;
        float b2x1 = ax  * DIV + w  * 0.5f, b2y1 = ay  * DIV + h  * 0.5f;

        float A  = (b1x1 - b1x0 + 1.0f) * (b1y1 - b1y0 + 1.0f);
        float Bt = (b2x1 - b2x0 + 1.0f) * (b2y1 - b2y0 + 1.0f);
        float CM = (fminf(b1x1, b2x1) - fmaxf(b1x0, b2x0) + 1.0f)
                 * (fminf(b1y1, b2y1) - fmaxf(b1y0, b2y0) + 1.0f);
        float iou = CM / (A + Bt - CM);
        iou = (iou < 0.0f) ? 0.0f : iou;

        float e0 = obj_pred - iou;
        float e1 = rax - ax;
        float e2 = ray - ay;
        float e3 = (rw - w) * INV_IMG;
        float e4 = (rh - h) * INV_IMG;

        acc += 5.0f * (e0*e0 + e1*e1 + e2*e2 + e3*e3 + e4*e4) * (1.0f / NB);
    }

    // Mask-scatter fence
    __syncthreads();

    // ---- Apply mask to preloaded noobj values + dedup count ----
    float no = 0.0f;
    int ccount = 0;
    if (tid < NWORDS) {
        unsigned int m = cleared32[tid];
        if (!(m & 0x000000FFu)) no += nv.x * nv.x;
        if (!(m & 0x0000FF00u)) no += nv.y * nv.y;
        if (!(m & 0x00FF0000u)) no += nv.z * nv.z;
        if (!(m & 0xFF000000u)) no += nv.w * nv.w;
        ccount = __popc(m);
    }

    // ---- Deterministic shuffle reduction over 16 warps ----
    #pragma unroll
    for (int off = 16; off > 0; off >>= 1) {
        acc    += __shfl_down_sync(0xFFFFFFFFu, acc,    off);
        no     += __shfl_down_sync(0xFFFFFFFFu, no,     off);
        ccount += __shfl_down_sync(0xFFFFFFFFu, ccount, off);
    }
    if (lane == 0) { sredA[warp] = acc; sredN[warp] = no; sredC[warp] = ccount; }
    __syncthreads();

    if (warp == 0) {
        float A  = (lane < 16) ? sredA[lane] : 0.0f;
        float Nn = (lane < 16) ? sredN[lane] : 0.0f;
        int   Cc = (lane < 16) ? sredC[lane] : 0;
        #pragma unroll
        for (int off = 8; off > 0; off >>= 1) {
            A  += __shfl_down_sync(0xFFFFFFFFu, A,  off);
            Nn += __shfl_down_sync(0xFFFFFFFFu, Nn, off);
            Cc += __shfl_down_sync(0xFFFFFFFFu, Cc, off);
        }
        if (lane == 0) {
            float cnt = (float)(OBJCELLS - Cc);
            g_img_loss[b] = A + 0.5f * Nn / cnt;
            __threadfence();
            unsigned int old = atomicAdd(&g_done_count, 1u);
            s_last = (old == BIMG - 1) ? 1 : 0;
        }
    }
    __syncthreads();

    // ---- Last block standing: deterministic final reduction of 256 partials ----
    if (s_last) {
        float v = (tid < BIMG) ? g_img_loss[tid] : 0.0f;
        #pragma unroll
        for (int off = 16; off > 0; off >>= 1)
            v += __shfl_down_sync(0xFFFFFFFFu, v, off);
        if (lane == 0) sredA[warp] = v;
        __syncthreads();
        if (warp == 0) {
            float t = (lane < 16) ? sredA[lane] : 0.0f;
            #pragma unroll
            for (int off = 8; off > 0; off >>= 1)
                t += __shfl_down_sync(0xFFFFFFFFu, t, off);
            if (lane == 0) {
                out[0] = t;
                atomicExch(&g_done_count, 0u);   // reset for next graph replay
            }
        }
    }
}

extern "C" void kernel_launch(void* const* d_in, const int* in_sizes, int n_in,
                              void* d_out, int out_size)
{
    const float* bx   = (const float*)d_in[0];
    const float* bbox = (const float*)d_in[1];
    const int*   bidx = (const int*)d_in[2];
    float* out = (float*)d_out;

    yolo_flat_kernel<<<BIMG, NTHR>>>(bx, bbox, bidx, out);
}

// round 10
// speedup vs baseline: 1.3851x; 1.0239x over previous
#include <cuda_runtime.h>
#include <math.h>

// Problem constants
#define SS        26
#define CC        80
#define CELLS     676        // 26*26
#define NB        32
#define BIMG      256
#define OBJCELLS  2028       // 3*676
#define NWORDS    (OBJCELLS/4)   // 507 float4 words
#define NCH       255        // 3*(5+80)
#define DIV       16.0f      // 416/26
#define INV_IMG   (1.0f/416.0f)
#define NTHR      128
#define NSLICE    4
#define GRID      (BIMG*NSLICE)   // 1024
#define WPS       127             // noobj float4 words per slice (last gets 126)

__constant__ float c_anchor[18] = {
    10.f,13.f, 16.f,30.f, 33.f,23.f, 30.f,61.f, 62.f,45.f,
    59.f,119.f, 116.f,90.f, 156.f,198.f, 373.f,326.f
};

__device__ float g_partial[GRID];
__device__ unsigned int g_done_count = 0;

// L2 evict_last via cache-policy register
__device__ __forceinline__ unsigned long long mk_policy() {
    unsigned long long pol;
    asm volatile("createpolicy.fractional.L2::evict_last.b64 %0, 1.0;" : "=l"(pol));
    return pol;
}
__device__ __forceinline__ float ldg_el(const float* p, unsigned long long pol) {
    float v;
    asm volatile("ld.global.nc.L2::cache_hint.f32 %0, [%1], %2;"
                 : "=f"(v) : "l"(p), "l"(pol));
    return v;
}
__device__ __forceinline__ float4 ldg_el4(const float* p, unsigned long long pol) {
    float4 v;
    asm volatile("ld.global.nc.L2::cache_hint.v4.f32 {%0,%1,%2,%3}, [%4], %5;"
                 : "=f"(v.x), "=f"(v.y), "=f"(v.z), "=f"(v.w) : "l"(p), "l"(pol));
    return v;
}

__global__ void __launch_bounds__(NTHR)
yolo_flat4_kernel(const float* __restrict__ bx,
                  const float* __restrict__ bbox,
                  const int*   __restrict__ bidx,
                  float* __restrict__ out)
{
    const int blk  = blockIdx.x;
    const int b    = blk >> 2;       // image
    const int s    = blk & 3;        // slice
    const int tid  = threadIdx.x;
    const int warp = tid >> 5;       // 4 warps
    const int lane = tid & 31;
    const float* __restrict__ x = bx + (size_t)b * NCH * CELLS;
    const unsigned long long pol = mk_policy();

    __shared__ unsigned int cleared32[NWORDS];
    __shared__ float sredA[4];
    __shared__ float sredN[4];
    __shared__ int   sredC[4];
    __shared__ int   s_last;

    unsigned char* cleared = (unsigned char*)cleared32;

    // Zero mask: 4 words per thread
    #pragma unroll
    for (int j = tid; j < NWORDS; j += NTHR) cleared32[j] = 0u;

    // ---- Per-thread box geometry from global (own label box) ----
    // thread t -> box bi = s*8 + (t>>4), classes c0 = (t&15)*5 .. +4
    const int bi = s * 8 + (tid >> 4);
    const int c0 = (tid & 15) * 5;
    const bool is_head = (tid & 15) == 0;

    const float* bp = bbox + ((size_t)b * NB + bi) * 5;
    float cls = bp[0], cx = bp[1], cy = bp[2], w = bp[3], h = bp[4];
    int nidx = bidx[b * NB + bi];
    int base = (nidx - 3) * 85;
    int ix = (int)(cx / DIV);
    int iy = (int)(cy / DIV);
    float ax = (cx - (float)ix * DIV) / DIV;
    float ay = (cy - (float)iy * DIV) / DIV;
    int o = ix * SS + iy;
    int cls_i = (int)cls;

    const float* p = x + (size_t)base * CELLS + o;

    // ---- Mask geometry for ALL 32 boxes (threads 0..31), computed from global ----
    int m_now = 0, m_o = 0;
    if (tid < NB) {
        const float* mp = bbox + ((size_t)b * NB + tid) * 5;
        float mcx = mp[1], mcy = mp[2];
        int mnidx = bidx[b * NB + tid];
        m_now = mnidx - 3;
        int mix = (int)(mcx / DIV);
        int miy = (int)(mcy / DIV);
        m_o = mix * SS + miy;
    }

    // ---- Issue ALL gathers now (label + head + noobj), fully overlapped ----
    float v0 = ldg_el(p + (size_t)(5 + c0 + 0) * CELLS, pol);
    float v1 = ldg_el(p + (size_t)(5 + c0 + 1) * CELLS, pol);
    float v2 = ldg_el(p + (size_t)(5 + c0 + 2) * CELLS, pol);
    float v3 = ldg_el(p + (size_t)(5 + c0 + 3) * CELLS, pol);
    float v4 = ldg_el(p + (size_t)(5 + c0 + 4) * CELLS, pol);

    float obj_pred = 0.f, rax = 0.f, ray = 0.f, t3 = 0.f, t4 = 0.f;
    if (is_head) {
        obj_pred = ldg_el(p + 0 * CELLS, pol);
        rax      = ldg_el(p + 1 * CELLS, pol);
        ray      = ldg_el(p + 2 * CELLS, pol);
        t3       = ldg_el(p + 3 * CELLS, pol);
        t4       = ldg_el(p + 4 * CELLS, pol);
    }

    float4 nv = make_float4(0.f, 0.f, 0.f, 0.f);
    const int j4 = s * WPS + tid;
    const bool has_no = (tid < WPS) && (j4 < NWORDS);
    if (has_no) {
        int r    = j4 / (CELLS / 4);
        int rem4 = j4 - r * (CELLS / 4);
        nv = ldg_el4(x + (size_t)(r * 85) * CELLS + rem4 * 4, pol);
    }

    // Mask-zero fence (loads above stay in flight across the barrier)
    __syncthreads();

    // Scatter cleared flags for all 32 boxes (duplicate writes of 1 benign)
    if (tid < NB) cleared[m_now * CELLS + m_o] = 1;

    // ---- Label MSE (overlaps with scatter settling) ----
    float acc;
    {
        float hot0 = (c0 + 0 == cls_i) ? 1.0f : 0.0f;
        float hot1 = (c0 + 1 == cls_i) ? 1.0f : 0.0f;
        float hot2 = (c0 + 2 == cls_i) ? 1.0f : 0.0f;
        float hot3 = (c0 + 3 == cls_i) ? 1.0f : 0.0f;
        float hot4 = (c0 + 4 == cls_i) ? 1.0f : 0.0f;
        float d0 = v0 - hot0, d1 = v1 - hot1, d2 = v2 - hot2,
              d3 = v3 - hot3, d4 = v4 - hot4;
        acc = (d0*d0 + d1*d1 + d2*d2 + d3*d3 + d4*d4) * (1.0f / (NB * CC));
    }

    // ---- Coord/obj loss on this slice's 8 head threads ----
    if (is_head) {
        float sig3 = 1.0f / (1.0f + __expf(-t3));
        float sig4 = 1.0f / (1.0f + __expf(-t4));
        float rw = c_anchor[nidx * 2 + 0] * __expf(4.0f * sig3 - 2.0f);
        float rh = c_anchor[nidx * 2 + 1] * __expf(4.0f * sig4 - 2.0f);

        float b1x0 = rax * DIV - rw * 0.5f, b1y0 = ray * DIV - rh * 0.5f;
        float b1x1 = rax * DIV + rw * 0.5f, b1y1 = ray * DIV + rh * 0.5f;
        float b2x0 = ax  * DIV - w  * 0.5f, b2y0 = ay  * DIV - h  * 0.5f;
        float b2x1 = ax  * DIV + w  * 0.5f, b2y1 = ay  * DIV + h  * 0.5f;

        float A  = (b1x1 - b1x0 + 1.0f) * (b1y1 - b1y0 + 1.0f);
        float Bt = (b2x1 - b2x0 + 1.0f) * (b2y1 - b2y0 + 1.0f);
        float CM = (fminf(b1x1, b2x1) - fmaxf(b1x0, b2x0) + 1.0f)
                 * (fminf(b1y1, b2y1) - fmaxf(b1y0, b2y0) + 1.0f);
        float iou = CM / (A + Bt - CM);
        iou = (iou < 0.0f) ? 0.0f : iou;

        float e0 = obj_pred - iou;
        float e1 = rax - ax;
        float e2 = ray - ay;
        float e3 = (rw - w) * INV_IMG;
        float e4 = (rh - h) * INV_IMG;

        acc += 5.0f * (e0*e0 + e1*e1 + e2*e2 + e3*e3 + e4*e4) * (1.0f / NB);
    }

    // Mask-scatter fence
    __syncthreads();

    // ---- Apply mask to preloaded noobj values; full dedup count per slice ----
    float no = 0.0f;
    if (has_no) {
        unsigned int m = cleared32[j4];
        if (!(m & 0x000000FFu)) no += nv.x * nv.x;
        if (!(m & 0x0000FF00u)) no += nv.y * nv.y;
        if (!(m & 0x00FF0000u)) no += nv.z * nv.z;
        if (!(m & 0xFF000000u)) no += nv.w * nv.w;
    }
    int ccount = 0;
    #pragma unroll
    for (int j = tid; j < NWORDS; j += NTHR) ccount += __popc(cleared32[j]);

    // ---- Deterministic shuffle reduction over 4 warps ----
    #pragma unroll
    for (int off = 16; off > 0; off >>= 1) {
        acc    += __shfl_down_sync(0xFFFFFFFFu, acc,    off);
        no     += __shfl_down_sync(0xFFFFFFFFu, no,     off);
        ccount += __shfl_down_sync(0xFFFFFFFFu, ccount, off);
    }
    if (lane == 0) { sredA[warp] = acc; sredN[warp] = no; sredC[warp] = ccount; }
    __syncthreads();

    if (tid == 0) {
        float A = sredA[0] + sredA[1] + sredA[2] + sredA[3];
        float Nn = sredN[0] + sredN[1] + sredN[2] + sredN[3];
        int   Cc = sredC[0] + sredC[1] + sredC[2] + sredC[3];
        float cnt = (float)(OBJCELLS - Cc);
        g_partial[blk] = A + 0.5f * Nn / cnt;
        __threadfence();
        unsigned int old = atomicAdd(&g_done_count, 1u);
        s_last = (old == GRID - 1) ? 1 : 0;
    }
    __syncthreads();

    // ---- Last block standing: deterministic fixed-order reduction of 1024 partials ----
    if (s_last) {
        float v = 0.0f;
        #pragma unroll
        for (int k = 0; k < GRID / NTHR; k++)
            v += g_partial[tid + k * NTHR];
        #pragma unroll
        for (int off = 16; off > 0; off >>= 1)
            v += __shfl_down_sync(0xFFFFFFFFu, v, off);
        if (lane == 0) sredA[warp] = v;
        __syncthreads();
        if (tid == 0) {
            out[0] = sredA[0] + sredA[1] + sredA[2] + sredA[3];
            atomicExch(&g_done_count, 0u);   // reset for next graph replay
        }
    }
}

extern "C" void kernel_launch(void* const* d_in, const int* in_sizes, int n_in,
                              void* d_out, int out_size)
{
    const float* bx   = (const float*)d_in[0];
    const float* bbox = (const float*)d_in[1];
    const int*   bidx = (const int*)d_in[2];
    float* out = (float*)d_out;

    yolo_flat4_kernel<<<GRID, NTHR>>>(bx, bbox, bidx, out);
}